// round 4
// baseline (speedup 1.0000x reference)
#include <cuda_runtime.h>

// LIF spike recurrence, T=8:
//   mem = mem*TAU + x[t]*alpha; spike = (mem > Vth); mem = spike ? 0 : mem
//
// Persistent grid (1216 CTAs = 152 SMs x 8 CTAs -> exactly one wave, no
// tail). __launch_bounds__(256, 8) forces regs <= 32 so all 8 CTAs/SM fit
// (R3 lesson: front-batched loads cost 48 regs -> 5 CTAs/SM -> DRAM% drop).
// Interleaved load/compute/store per timestep keeps live registers low;
// cross-iteration MLP comes from occupancy, not per-thread batching.

#define TAU 0.5f
#define NUM_CTAS 1216
#define THREADS  256

__global__ void __launch_bounds__(THREADS, 8) lif_spike_kernel(
    const float4* __restrict__ x,
    const float* __restrict__ alpha_p,
    const float* __restrict__ vth_p,
    float4* __restrict__ out,
    int ncols /* spatial/4, float4 columns per timestep */)
{
    const float alpha = __ldg(alpha_p);
    const float vth   = __ldg(vth_p);

    for (int col = blockIdx.x * THREADS + threadIdx.x; col < ncols;
         col += NUM_CTAS * THREADS) {

        const float4* __restrict__ xp = x + col;
        float4* __restrict__ op = out + col;

        float m0 = 0.f, m1 = 0.f, m2 = 0.f, m3 = 0.f;

        #pragma unroll
        for (int t = 0; t < 8; t++) {
            const float4 xt = xp[t * ncols];

            m0 = m0 * TAU + xt.x * alpha;
            m1 = m1 * TAU + xt.y * alpha;
            m2 = m2 * TAU + xt.z * alpha;
            m3 = m3 * TAU + xt.w * alpha;

            float4 s;
            s.x = (m0 > vth) ? 1.f : 0.f;
            s.y = (m1 > vth) ? 1.f : 0.f;
            s.z = (m2 > vth) ? 1.f : 0.f;
            s.w = (m3 > vth) ? 1.f : 0.f;

            m0 = (m0 > vth) ? 0.f : m0;
            m1 = (m1 > vth) ? 0.f : m1;
            m2 = (m2 > vth) ? 0.f : m2;
            m3 = (m3 > vth) ? 0.f : m3;

            op[t * ncols] = s;
        }
    }
}

extern "C" void kernel_launch(void* const* d_in, const int* in_sizes, int n_in,
                              void* d_out, int out_size) {
    const float* x     = (const float*)d_in[0];
    const float* alpha = (const float*)d_in[1];
    const float* vth   = (const float*)d_in[2];
    float* out = (float*)d_out;

    const int total   = in_sizes[0];   // T * spatial
    const int spatial = total / 8;     // T = 8
    const int ncols   = spatial / 4;   // float4 columns (spatial % 4 == 0)

    lif_spike_kernel<<<NUM_CTAS, THREADS>>>(
        (const float4*)x, alpha, vth, (float4*)out, ncols);
}

// round 5
// speedup vs baseline: 1.0539x; 1.0539x over previous
#include <cuda_runtime.h>

// LIF spike recurrence, T=8:
//   mem = mem*TAU + x[t]*alpha; spike = (mem > Vth); mem = spike ? 0 : mem
//
// At the streaming roofline (~7.4 TB/s effective for 268 MB mixed r/w; ncu
// dur pinned at ~36us across 4 structural variants). Remaining lever is
// inter-replay L2 writeback interference in the timed graph loop:
// __stcs stores drain output lines promptly so the next replay's read
// stream doesn't collide with this replay's writebacks (R2 evidence).
// Interleaved body + launch_bounds(256,8) keeps regs at 32 -> 8 CTAs/SM.

#define TAU 0.5f
#define THREADS 256

__global__ void __launch_bounds__(THREADS, 8) lif_spike_kernel(
    const float4* __restrict__ x,
    const float* __restrict__ alpha_p,
    const float* __restrict__ vth_p,
    float4* __restrict__ out,
    int ncols /* spatial/4, float4 columns per timestep */)
{
    const float alpha = __ldg(alpha_p);
    const float vth   = __ldg(vth_p);

    const int col = blockIdx.x * THREADS + threadIdx.x;
    if (col >= ncols) return;

    const float4* __restrict__ xp = x + col;
    float4* __restrict__ op = out + col;

    float m0 = 0.f, m1 = 0.f, m2 = 0.f, m3 = 0.f;

    #pragma unroll
    for (int t = 0; t < 8; t++) {
        const float4 xt = __ldcs(xp + t * ncols);

        m0 = m0 * TAU + xt.x * alpha;
        m1 = m1 * TAU + xt.y * alpha;
        m2 = m2 * TAU + xt.z * alpha;
        m3 = m3 * TAU + xt.w * alpha;

        float4 s;
        s.x = (m0 > vth) ? 1.f : 0.f;
        s.y = (m1 > vth) ? 1.f : 0.f;
        s.z = (m2 > vth) ? 1.f : 0.f;
        s.w = (m3 > vth) ? 1.f : 0.f;

        m0 = (m0 > vth) ? 0.f : m0;
        m1 = (m1 > vth) ? 0.f : m1;
        m2 = (m2 > vth) ? 0.f : m2;
        m3 = (m3 > vth) ? 0.f : m3;

        __stcs(op + t * ncols, s);
    }
}

extern "C" void kernel_launch(void* const* d_in, const int* in_sizes, int n_in,
                              void* d_out, int out_size) {
    const float* x     = (const float*)d_in[0];
    const float* alpha = (const float*)d_in[1];
    const float* vth   = (const float*)d_in[2];
    float* out = (float*)d_out;

    const int total   = in_sizes[0];   // T * spatial
    const int spatial = total / 8;     // T = 8
    const int ncols   = spatial / 4;   // float4 columns (spatial % 4 == 0)

    const int blocks = (ncols + THREADS - 1) / THREADS;
    lif_spike_kernel<<<blocks, THREADS>>>(
        (const float4*)x, alpha, vth, (float4*)out, ncols);
}